// round 15
// baseline (speedup 1.0000x reference)
#include <cuda_runtime.h>
#include <cuda_fp16.h>
#include <cstdint>

// Problem constants
#define BB   8
#define CC   1024
#define HH   64
#define WW   64
#define NHD  16
#define HD   64
#define HWP  4096
#define CHW  (CC * HWP)
#define EPSB 1e-3f

// Scale folding: W stored x2^14, X stored x2^10, epilogue multiplies 2^-24.
#define WSCALE 16384.0f
#define XSCALE 1024.0f
#define INV_S  5.9604644775390625e-8f   // 2^-24

// GEMM tiling (R8-proven: 128x128, BK=64, 2-stage, 2 CTAs/SM)
#define BM   128
#define BN   128
#define BKE  64
#define LDT  72              // padded SMEM row (elems) = 144B
#define NKT  (CC / BKE)      // 16

#define TILE_B   (128 * LDT * 2)          // 18432 B
#define STAGE_B  (2 * TILE_B)
#define SMEM_TOT (2 * STAGE_B)            // 73728 B -> 2 CTAs/SM

// dwconv v3: channel-last, 8x8 pixel tile, full 1024 channels, 10x10 halo
#define DW_SMEM_T (100 * CC * 2)          // 204800 B -> 1 CTA/SM

// attention: k-major layout, 144B rows
#define LDK  72

// ---------------------------------------------------------------------------
// Scratch (device globals)
// ---------------------------------------------------------------------------
__device__ __half g_y1h[BB * CHW];       // conv1 output (fp16), [b][c][p]
__device__ __half g_y2t[BB * CHW];       // attention output (fp16), [b][p][c]
__device__ __half g_w1h[CC * CC];
__device__ __half g_w3h[CC * CC];
__device__ __half g_bh[BB * HWP * CC];   // transposed activations [b][p][ci]

// ---------------------------------------------------------------------------
// PTX helpers
// ---------------------------------------------------------------------------
__device__ __forceinline__ uint32_t smem_u32(const void* p) {
    uint32_t a;
    asm("{ .reg .u64 t; cvta.to.shared.u64 t, %1; cvt.u32.u64 %0, t; }" : "=r"(a) : "l"(p));
    return a;
}
__device__ __forceinline__ void cp_async16(uint32_t saddr, const void* gaddr) {
    asm volatile("cp.async.cg.shared.global [%0], [%1], 16;" :: "r"(saddr), "l"(gaddr));
}
__device__ __forceinline__ void cp_commit() {
    asm volatile("cp.async.commit_group;" ::: "memory");
}
template <int N>
__device__ __forceinline__ void cp_wait() {
    asm volatile("cp.async.wait_group %0;" :: "n"(N) : "memory");
}
__device__ __forceinline__ void ldmx4(uint32_t* r, uint32_t addr) {
    asm volatile("ldmatrix.sync.aligned.m8n8.x4.shared.b16 {%0,%1,%2,%3}, [%4];"
                 : "=r"(r[0]), "=r"(r[1]), "=r"(r[2]), "=r"(r[3]) : "r"(addr));
}
__device__ __forceinline__ void ldmx4t(uint32_t* r, uint32_t addr) {
    asm volatile("ldmatrix.sync.aligned.m8n8.x4.trans.shared.b16 {%0,%1,%2,%3}, [%4];"
                 : "=r"(r[0]), "=r"(r[1]), "=r"(r[2]), "=r"(r[3]) : "r"(addr));
}
__device__ __forceinline__ void mma16816(float* c, const uint32_t* a,
                                         uint32_t b0, uint32_t b1) {
    asm volatile(
        "mma.sync.aligned.m16n8k16.row.col.f32.f16.f16.f32 "
        "{%0,%1,%2,%3}, {%4,%5,%6,%7}, {%8,%9}, {%0,%1,%2,%3};"
        : "+f"(c[0]), "+f"(c[1]), "+f"(c[2]), "+f"(c[3])
        : "r"(a[0]), "r"(a[1]), "r"(a[2]), "r"(a[3]), "r"(b0), "r"(b1));
}
__device__ __forceinline__ float silu(float y) {
    return y * (1.f / (1.f + __expf(-y)));
}

// ---------------------------------------------------------------------------
// Converters
// ---------------------------------------------------------------------------
__global__ void convert_w2_kernel(const float* __restrict__ W1,
                                  const float* __restrict__ W3,
                                  __half* __restrict__ O1,
                                  __half* __restrict__ O3)
{
    int i = blockIdx.x * blockDim.x + threadIdx.x;
    if (i < CC * CC) {
        O1[i] = __float2half_rn(W1[i] * WSCALE);
        O3[i] = __float2half_rn(W3[i] * WSCALE);
    }
}

// Transpose+convert: X fp32 [b][ci][p] -> fp16 [b][p][ci], scaled by XSCALE.
__global__ __launch_bounds__(256)
void transpose_cvt_kernel(const float* __restrict__ X,
                          __half* __restrict__ Th)
{
    __shared__ float t[64][33];
    const int p0 = blockIdx.x * 32;
    const int c0 = blockIdx.y * 64;
    const int b  = blockIdx.z;
    const int tid = threadIdx.x;

    const float* Xb = X + (size_t)b * CHW;
#pragma unroll
    for (int j = 0; j < 8; j++) {
        int i = j * 256 + tid;
        int r = i >> 5, cl = i & 31;
        t[r][cl] = Xb[(size_t)(c0 + r) * HWP + p0 + cl];
    }
    __syncthreads();

    __half* Tp = Th + (size_t)b * HWP * CC;
    const int cp = tid & 31;
#pragma unroll
    for (int j = 0; j < 4; j++) {
        int p = (tid >> 5) + j * 8;
        __half2 v = __floats2half2_rn(t[2 * cp][p] * XSCALE,
                                      t[2 * cp + 1][p] * XSCALE);
        *(__half2*)&Tp[(size_t)(p0 + p) * CC + c0 + 2 * cp] = v;
    }
}

// ---------------------------------------------------------------------------
// Warp-MMA fp16 GEMM + BN + SiLU. HALF_OUT: fp16 store, no residual.
// ---------------------------------------------------------------------------
template <bool HALF_OUT>
__global__ __launch_bounds__(256, 2)
void gemm_mma_kernel(const __half* __restrict__ Ah,
                     const __half* __restrict__ Bh_,
                     const float* __restrict__ gam,
                     const float* __restrict__ bet,
                     const float* __restrict__ mu,
                     const float* __restrict__ var,
                     const float* __restrict__ res,
                     void* __restrict__ outv)
{
    extern __shared__ char smem[];
    const uint32_t sb = smem_u32(smem);

    const int tid  = threadIdx.x;
    const int warp = tid >> 5, lane = tid & 31;
    const int warp_m = warp >> 2;
    const int warp_n = warp & 3;

    const int n0 = blockIdx.x * BN;
    const int m0 = blockIdx.y * BM;
    const int bz = blockIdx.z;
    const __half* Bh = Bh_ + (size_t)bz * HWP * CC;

    float acc[4][4][4];
#pragma unroll
    for (int i = 0; i < 4; i++)
#pragma unroll
        for (int j = 0; j < 4; j++)
#pragma unroll
            for (int q = 0; q < 4; q++) acc[i][j][q] = 0.f;

    const __half* apt[4];
    const __half* bpt[4];
    uint32_t soff[4];
#pragma unroll
    for (int j = 0; j < 4; j++) {
        int rc = tid + j * 256;
        int row = rc >> 3, c = (rc & 7) * 8;
        soff[j] = (row * LDT + c) * 2;
        apt[j] = Ah + (size_t)(m0 + row) * CC + c;
        bpt[j] = Bh + (size_t)(n0 + row) * CC + c;
    }

    auto stage = [&](int it) {
        const uint32_t st = sb + (it & 1) * STAGE_B;
        const int kt = it * BKE;
#pragma unroll
        for (int j = 0; j < 4; j++) {
            cp_async16(st + soff[j], apt[j] + kt);
            cp_async16(st + TILE_B + soff[j], bpt[j] + kt);
        }
        cp_commit();
    };

    const int lr = lane & 15;
    const int lh = (lane >> 4) * 8;

    stage(0);

    for (int it = 0; it < NKT; it++) {
        if (it + 1 < NKT) {
            stage(it + 1);
            cp_wait<1>();
        } else {
            cp_wait<0>();
        }
        __syncthreads();

        const uint32_t st = sb + (it & 1) * STAGE_B;
#pragma unroll
        for (int kh = 0; kh < 4; kh++) {
            const int k16 = kh * 16;
            uint32_t af[4][4];
#pragma unroll
            for (int mt = 0; mt < 4; mt++)
                ldmx4(af[mt], st + ((warp_m * 64 + mt * 16 + lr) * LDT + k16 + lh) * 2);
            uint32_t bf[2][4];
#pragma unroll
            for (int nt2 = 0; nt2 < 2; nt2++)
                ldmx4(bf[nt2], st + TILE_B +
                      ((warp_n * 32 + nt2 * 16 + lr) * LDT + k16 + lh) * 2);
#pragma unroll
            for (int mt = 0; mt < 4; mt++)
#pragma unroll
                for (int nt = 0; nt < 4; nt++)
                    mma16816(acc[mt][nt], af[mt],
                             bf[nt >> 1][nt & 1], bf[nt >> 1][(nt & 1) + 2]);
        }
        __syncthreads();
    }

    const int qrow = lane >> 2;
    const int qcol = (lane & 3) * 2;
#pragma unroll
    for (int mt = 0; mt < 4; mt++) {
#pragma unroll
        for (int half = 0; half < 2; half++) {
            const int co = m0 + warp_m * 64 + mt * 16 + qrow + half * 8;
            const float sc0 = gam[co] * rsqrtf(var[co] + EPSB);
            const float bi = bet[co] - mu[co] * sc0;
            const float sc = sc0 * INV_S;
            const size_t rbase = (size_t)bz * CHW + (size_t)co * HWP + n0 + warp_n * 32;
#pragma unroll
            for (int nt = 0; nt < 4; nt++) {
                const int nn = nt * 8 + qcol;
                float y0 = silu(acc[mt][nt][half * 2 + 0] * sc + bi);
                float y1 = silu(acc[mt][nt][half * 2 + 1] * sc + bi);
                if (HALF_OUT) {
                    __half* orow = (__half*)outv + rbase;
                    *(__half2*)&orow[nn] = __floats2half2_rn(y0, y1);
                } else {
                    float* orow = (float*)outv + rbase;
                    const float* rrow = res + rbase;
                    y0 += rrow[nn];
                    y1 += rrow[nn + 1];
                    *(float2*)&orow[nn] = make_float2(y0, y1);
                }
            }
        }
    }
}

// ---------------------------------------------------------------------------
// K2: per-(b,nh,h) softmax-attention, k-major smem + trans ldmatrix.
// Writes y2 TRANSPOSED: y2t[b][p][c] (channel-last for dwconv).
// ---------------------------------------------------------------------------
__global__ __launch_bounds__(256)
void attn_kernel(const __half* __restrict__ Y1, __half* __restrict__ Y2t)
{
    const int bid = blockIdx.x;
    const int h  = bid & 63;
    const int nh = (bid >> 6) & 15;
    const int b  = bid >> 10;

    const __half* basep = Y1 + (size_t)b * CHW + (size_t)(nh * HD) * HWP + h * WW;

    __shared__ __half Ak[64 * LDK];    // [k][w]
    __shared__ __half Ps[64 * LDK];    // [k][w] exp; later reused as att[w][v]
    __shared__ float red[4 * 64];
    __shared__ float mx_s[64];
    __shared__ float inv_s[64];

    const int tid = threadIdx.x;
    const int lane = tid & 31, warp = tid >> 5;

    // coalesced load, k-major (no transpose)
#pragma unroll
    for (int j = 0; j < 2; j++) {
        int idx = j * 256 + tid;
        int k = idx >> 3, c = idx & 7;
        uint4 v = *(const uint4*)(basep + (size_t)k * HWP + c * 8);
        *(uint4*)&Ak[k * LDK + c * 8] = v;
    }
    __syncthreads();

    // column softmax: thread (w, seg) handles k in [seg*16, seg*16+16)
    const int w = tid & 63, seg = tid >> 6;
    __half av[16];
    float mx = -1e30f;
#pragma unroll
    for (int i = 0; i < 16; i++) {
        av[i] = Ak[(seg * 16 + i) * LDK + w];
        mx = fmaxf(mx, __half2float(av[i]));
    }
    red[seg * 64 + w] = mx;
    __syncthreads();
    if (tid < 64)
        mx_s[tid] = fmaxf(fmaxf(red[tid], red[64 + tid]),
                          fmaxf(red[128 + tid], red[192 + tid]));
    __syncthreads();

    const float mw = mx_s[w];
    float sum = 0.f;
#pragma unroll
    for (int i = 0; i < 16; i++) {
        float e = __expf(__half2float(av[i]) - mw);
        sum += e;
        Ps[(seg * 16 + i) * LDK + w] = __float2half_rn(e);
    }
    red[seg * 64 + w] = sum;
    __syncthreads();
    if (tid < 64)
        inv_s[tid] = 1.f / (red[tid] + red[64 + tid] + red[128 + tid] + red[192 + tid]);
    __syncthreads();

    // MMA: warp tile 16(w) x 32(v); both operands via trans ldmatrix
    const uint32_t pk = smem_u32(Ps);
    const uint32_t ak = smem_u32(Ak);
    const int m0 = (warp & 3) * 16;        // w base
    const int nw0 = (warp >> 2) * 32;      // v base
    const int kpart = (lane >> 4) * 8 + (lane & 7);
    const int cpart = ((lane >> 3) & 1) * 8;

    float acc[4][4];
#pragma unroll
    for (int i = 0; i < 4; i++)
#pragma unroll
        for (int q = 0; q < 4; q++) acc[i][q] = 0.f;

#pragma unroll
    for (int kh = 0; kh < 4; kh++) {
        const int krow = kh * 16 + kpart;
        uint32_t a[4];
        ldmx4t(a, pk + (krow * LDK + m0 + cpart) * 2);
        uint32_t bf[2][4];
#pragma unroll
        for (int g = 0; g < 2; g++)
            ldmx4t(bf[g], ak + (krow * LDK + nw0 + g * 16 + cpart) * 2);
#pragma unroll
        for (int nt = 0; nt < 4; nt++)
            mma16816(acc[nt], a, bf[nt >> 1][nt & 1], bf[nt >> 1][(nt & 1) + 2]);
    }
    __syncthreads();   // done reading Ps/Ak; reuse Ps as att[w][v]

    // scale by inv[w]; stage att[w][v] (natural orientation for [p][c] store)
    const int qrow = lane >> 2;
    const int qcol = (lane & 3) * 2;
    const float inv0 = inv_s[m0 + qrow];
    const float inv1 = inv_s[m0 + qrow + 8];
#pragma unroll
    for (int nt = 0; nt < 4; nt++) {
        const int v = nw0 + nt * 8 + qcol;
        *(__half2*)&Ps[(m0 + qrow) * LDK + v] =
            __floats2half2_rn(acc[nt][0] * inv0, acc[nt][1] * inv0);
        *(__half2*)&Ps[(m0 + qrow + 8) * LDK + v] =
            __floats2half2_rn(acc[nt][2] * inv1, acc[nt][3] * inv1);
    }
    __syncthreads();

    // store channel-last: y2t[(h*64+w)*CC + nh*64 + v], 128B contiguous rows
    __half* outb = Y2t + (size_t)b * CHW + (size_t)(h * 64) * CC + nh * 64;
#pragma unroll
    for (int j = 0; j < 2; j++) {
        int idx = j * 256 + tid;
        int w2 = idx >> 3, c = idx & 7;
        *(uint4*)(outb + (size_t)w2 * CC + c * 8) = *(const uint4*)&Ps[w2 * LDK + c * 8];
    }
}

// ---------------------------------------------------------------------------
// K3 v3: channel-last depthwise 3x3 + BN + SiLU + fp16 convert.
// CTA = (b, 8x8 pixel tile) x ALL 1024 channels. smem holds 10x10 halo
// x 1024 ch (200KB). Per (pixel, 8ch-group): 9 uint4 LDS (was 72 scalar).
// Thread owns ONE fixed 8-ch group (tid & 127): weights live in registers.
// ---------------------------------------------------------------------------
__global__ __launch_bounds__(256)
void dwconv_t_kernel(const __half* __restrict__ Y2t,
                     const float* __restrict__ W2,
                     const float* __restrict__ gam,
                     const float* __restrict__ bet,
                     const float* __restrict__ mu,
                     const float* __restrict__ var,
                     __half* __restrict__ Th)
{
    extern __shared__ __half S[];          // [100 halo px][1024 ch]
    const int tile = blockIdx.x;           // 0..63
    const int b    = blockIdx.y;
    const int ty0  = (tile >> 3) * 8;
    const int tx0  = (tile & 7) * 8;
    const int tid  = threadIdx.x;

    const __half* src = Y2t + (size_t)b * CHW;   // [p][c]

    // halo load: 100 pixel-rows x 2KB, coalesced; OOB rows/cols zeroed
#pragma unroll
    for (int j = 0; j < 50; j++) {
        int idx = j * 256 + tid;               // 0..12799
        int hp  = idx >> 7, c16 = idx & 127;
        int hy  = (hp * 205) >> 11;            // hp / 10
        int hx  = hp - hy * 10;
        int gy  = ty0 - 1 + hy, gx = tx0 - 1 + hx;
        uint4 v = make_uint4(0, 0, 0, 0);
        if ((unsigned)gy < 64u && (unsigned)gx < 64u)
            v = *(const uint4*)(src + (size_t)(gy * 64 + gx) * CC + c16 * 8);
        *(uint4*)(S + hp * CC + c16 * 8) = v;
    }

    // per-thread channel group
    const int g  = tid & 127;
    const int cb = g * 8;
    float w[8][9], sc[8], bi[8];
#pragma unroll
    for (int ch = 0; ch < 8; ch++) {
        const int c = cb + ch;
#pragma unroll
        for (int k = 0; k < 9; k++) w[ch][k] = W2[c * 9 + k];
        const float s0 = gam[c] * rsqrtf(var[c] + EPSB);
        sc[ch] = s0;
        bi[ch] = bet[c] - mu[c] * s0;
    }
    __syncthreads();

    __half* outp = Th + (size_t)b * HWP * CC;
#pragma unroll 2
    for (int j = 0; j < 32; j++) {
        const int u  = tid + j * 256;
        const int px = u >> 7;                 // 0..63 (tile-local pixel)
        const int py = px >> 3, pxx = px & 7;
        float acc[8] = {0.f, 0.f, 0.f, 0.f, 0.f, 0.f, 0.f, 0.f};
#pragma unroll
        for (int dy = 0; dy < 3; dy++)
#pragma unroll
            for (int dx = 0; dx < 3; dx++) {
                const int hp = (py + dy) * 10 + pxx + dx;
                const uint4 t = *(const uint4*)(S + hp * CC + cb);
                const __half2* h2 = (const __half2*)&t;
                const float wk = 0.f;          // (unused; keep regs tight)
                (void)wk;
#pragma unroll
                for (int q = 0; q < 4; q++) {
                    float2 v = __half22float2(h2[q]);
                    acc[2 * q + 0] = fmaf(w[2 * q + 0][dy * 3 + dx], v.x, acc[2 * q + 0]);
                    acc[2 * q + 1] = fmaf(w[2 * q + 1][dy * 3 + dx], v.y, acc[2 * q + 1]);
                }
            }
        __half h8[8];
#pragma unroll
        for (int ch = 0; ch < 8; ch++) {
            float s = silu(acc[ch] * sc[ch] + bi[ch]);
            h8[ch] = __float2half_rn(s * XSCALE);
        }
        const int gp = (ty0 + py) * 64 + tx0 + pxx;
        *(uint4*)(outp + (size_t)gp * CC + cb) = *(uint4*)h8;
    }
}

// ---------------------------------------------------------------------------
// Launch. setup_inputs() dict order:
//   0:x 1:w1 2:w2 3:w3 4:g1 5:b1 6:m1 7:v1 8:g2 9:b2 10:m2 11:v2 12:g3 13:b3 14:m3 15:v3
// ---------------------------------------------------------------------------
extern "C" void kernel_launch(void* const* d_in, const int* in_sizes, int n_in,
                              void* d_out, int out_size)
{
    const float* x  = (const float*)d_in[0];
    const float* w1 = (const float*)d_in[1];
    const float* w2 = (const float*)d_in[2];
    const float* w3 = (const float*)d_in[3];
    const float* g1 = (const float*)d_in[4];
    const float* b1 = (const float*)d_in[5];
    const float* m1 = (const float*)d_in[6];
    const float* v1 = (const float*)d_in[7];
    const float* g2 = (const float*)d_in[8];
    const float* b2 = (const float*)d_in[9];
    const float* m2 = (const float*)d_in[10];
    const float* v2 = (const float*)d_in[11];
    const float* g3 = (const float*)d_in[12];
    const float* b3 = (const float*)d_in[13];
    const float* m3 = (const float*)d_in[14];
    const float* v3 = (const float*)d_in[15];
    float* out = (float*)d_out;

    if (!(in_sizes[1] == CC * CC && in_sizes[2] == CC * 9 && in_sizes[3] == CC * CC)) {
        const float* big[2] = {nullptr, nullptr}; int nbig = 0;
        const float* small9216 = nullptr;
        const float* perch[12]; int nper = 0;
        for (int i = 1; i < n_in; i++) {
            if (in_sizes[i] == CC * CC && nbig < 2) big[nbig++] = (const float*)d_in[i];
            else if (in_sizes[i] == CC * 9) small9216 = (const float*)d_in[i];
            else if (in_sizes[i] == CC && nper < 12) perch[nper++] = (const float*)d_in[i];
        }
        w1 = big[0]; w3 = big[1]; w2 = small9216;
        g1 = perch[0]; b1 = perch[1]; m1 = perch[2];  v1 = perch[3];
        g2 = perch[4]; b2 = perch[5]; m2 = perch[6];  v2 = perch[7];
        g3 = perch[8]; b3 = perch[9]; m3 = perch[10]; v3 = perch[11];
    }

    __half *p_y1h, *p_y2t, *p_w1h, *p_w3h, *p_bh;
    cudaGetSymbolAddress((void**)&p_y1h, g_y1h);
    cudaGetSymbolAddress((void**)&p_y2t, g_y2t);
    cudaGetSymbolAddress((void**)&p_w1h, g_w1h);
    cudaGetSymbolAddress((void**)&p_w3h, g_w3h);
    cudaGetSymbolAddress((void**)&p_bh, g_bh);

    cudaFuncSetAttribute(gemm_mma_kernel<true>,
                         cudaFuncAttributeMaxDynamicSharedMemorySize, SMEM_TOT);
    cudaFuncSetAttribute(gemm_mma_kernel<false>,
                         cudaFuncAttributeMaxDynamicSharedMemorySize, SMEM_TOT);
    cudaFuncSetAttribute(dwconv_t_kernel,
                         cudaFuncAttributeMaxDynamicSharedMemorySize, DW_SMEM_T);

    dim3 tgrid(HWP / 32, CC / 64, BB);
    dim3 ggrid(HWP / BN, CC / BM, BB);     // (32, 8, 8)
    dim3 dgrid(64, BB);                    // 8x8 tiles x batch

    convert_w2_kernel<<<(CC * CC + 511) / 512, 512>>>(w1, w3, p_w1h, p_w3h);
    transpose_cvt_kernel<<<tgrid, 256>>>(x, p_bh);
    gemm_mma_kernel<true><<<ggrid, 256, SMEM_TOT>>>(p_w1h, p_bh,
                                                    g1, b1, m1, v1, nullptr, p_y1h);
    attn_kernel<<<BB * NHD * HH, 256>>>(p_y1h, p_y2t);
    dwconv_t_kernel<<<dgrid, 256, DW_SMEM_T>>>(p_y2t, w2, g2, b2, m2, v2, p_bh);
    gemm_mma_kernel<false><<<ggrid, 256, SMEM_TOT>>>(p_w3h, p_bh,
                                                     g3, b3, m3, v3, x, out);
}

// round 16
// speedup vs baseline: 1.0953x; 1.0953x over previous
#include <cuda_runtime.h>
#include <cuda_fp16.h>
#include <cstdint>

// Problem constants
#define BB   8
#define CC   1024
#define HH   64
#define WW   64
#define NHD  16
#define HD   64
#define HWP  4096
#define CHW  (CC * HWP)
#define EPSB 1e-3f

// Scale folding: W stored x2^14, X stored x2^10, epilogue multiplies 2^-24.
#define WSCALE 16384.0f
#define XSCALE 1024.0f
#define INV_S  5.9604644775390625e-8f   // 2^-24

// GEMM tiling (R8-proven: 128x128, BK=64, 2-stage, 2 CTAs/SM)
#define BM   128
#define BN   128
#define BKE  64
#define LDT  72              // padded SMEM row (elems) = 144B
#define NKT  (CC / BKE)      // 16

#define TILE_B   (128 * LDT * 2)          // 18432 B
#define STAGE_B  (2 * TILE_B)
#define SMEM_TOT (2 * STAGE_B)            // 73728 B -> 2 CTAs/SM

// dwconv: 8 fp16 planes, 2 px/thread via half2 loads
#define DWC  8
#define DW_SMEM_H (DWC * HWP * 2)         // 65536 B -> 2 CTAs/SM

// attention: k-major layout, 144B rows
#define LDK  72

// ---------------------------------------------------------------------------
// Scratch (device globals)
// ---------------------------------------------------------------------------
__device__ __half g_y1h[BB * CHW];       // conv1 output (fp16), [b][c][p]
__device__ __half g_y2h[BB * CHW];       // attention output (fp16), [b][c][p]
__device__ __half g_w1h[CC * CC];
__device__ __half g_w3h[CC * CC];
__device__ __half g_bh[BB * HWP * CC];   // transposed activations [b][p][ci]

// ---------------------------------------------------------------------------
// PTX helpers
// ---------------------------------------------------------------------------
__device__ __forceinline__ uint32_t smem_u32(const void* p) {
    uint32_t a;
    asm("{ .reg .u64 t; cvta.to.shared.u64 t, %1; cvt.u32.u64 %0, t; }" : "=r"(a) : "l"(p));
    return a;
}
__device__ __forceinline__ void cp_async16(uint32_t saddr, const void* gaddr) {
    asm volatile("cp.async.cg.shared.global [%0], [%1], 16;" :: "r"(saddr), "l"(gaddr));
}
__device__ __forceinline__ void cp_commit() {
    asm volatile("cp.async.commit_group;" ::: "memory");
}
template <int N>
__device__ __forceinline__ void cp_wait() {
    asm volatile("cp.async.wait_group %0;" :: "n"(N) : "memory");
}
__device__ __forceinline__ void ldmx4(uint32_t* r, uint32_t addr) {
    asm volatile("ldmatrix.sync.aligned.m8n8.x4.shared.b16 {%0,%1,%2,%3}, [%4];"
                 : "=r"(r[0]), "=r"(r[1]), "=r"(r[2]), "=r"(r[3]) : "r"(addr));
}
__device__ __forceinline__ void ldmx4t(uint32_t* r, uint32_t addr) {
    asm volatile("ldmatrix.sync.aligned.m8n8.x4.trans.shared.b16 {%0,%1,%2,%3}, [%4];"
                 : "=r"(r[0]), "=r"(r[1]), "=r"(r[2]), "=r"(r[3]) : "r"(addr));
}
__device__ __forceinline__ void mma16816(float* c, const uint32_t* a,
                                         uint32_t b0, uint32_t b1) {
    asm volatile(
        "mma.sync.aligned.m16n8k16.row.col.f32.f16.f16.f32 "
        "{%0,%1,%2,%3}, {%4,%5,%6,%7}, {%8,%9}, {%0,%1,%2,%3};"
        : "+f"(c[0]), "+f"(c[1]), "+f"(c[2]), "+f"(c[3])
        : "r"(a[0]), "r"(a[1]), "r"(a[2]), "r"(a[3]), "r"(b0), "r"(b1));
}
__device__ __forceinline__ float silu(float y) {
    return y * (1.f / (1.f + __expf(-y)));
}

// ---------------------------------------------------------------------------
// Converters
// ---------------------------------------------------------------------------
__global__ void convert_w2_kernel(const float* __restrict__ W1,
                                  const float* __restrict__ W3,
                                  __half* __restrict__ O1,
                                  __half* __restrict__ O3)
{
    int i = blockIdx.x * blockDim.x + threadIdx.x;
    if (i < CC * CC) {
        O1[i] = __float2half_rn(W1[i] * WSCALE);
        O3[i] = __float2half_rn(W3[i] * WSCALE);
    }
}

// Transpose+convert: X fp32 [b][ci][p] -> fp16 [b][p][ci], scaled by XSCALE.
__global__ __launch_bounds__(256)
void transpose_cvt_kernel(const float* __restrict__ X,
                          __half* __restrict__ Th)
{
    __shared__ float t[64][33];
    const int p0 = blockIdx.x * 32;
    const int c0 = blockIdx.y * 64;
    const int b  = blockIdx.z;
    const int tid = threadIdx.x;

    const float* Xb = X + (size_t)b * CHW;
#pragma unroll
    for (int j = 0; j < 8; j++) {
        int i = j * 256 + tid;
        int r = i >> 5, cl = i & 31;
        t[r][cl] = Xb[(size_t)(c0 + r) * HWP + p0 + cl];
    }
    __syncthreads();

    __half* Tp = Th + (size_t)b * HWP * CC;
    const int cp = tid & 31;
#pragma unroll
    for (int j = 0; j < 4; j++) {
        int p = (tid >> 5) + j * 8;
        __half2 v = __floats2half2_rn(t[2 * cp][p] * XSCALE,
                                      t[2 * cp + 1][p] * XSCALE);
        *(__half2*)&Tp[(size_t)(p0 + p) * CC + c0 + 2 * cp] = v;
    }
}

// ---------------------------------------------------------------------------
// Warp-MMA fp16 GEMM + BN + SiLU. HALF_OUT: fp16 store, no residual.
// ---------------------------------------------------------------------------
template <bool HALF_OUT>
__global__ __launch_bounds__(256, 2)
void gemm_mma_kernel(const __half* __restrict__ Ah,
                     const __half* __restrict__ Bh_,
                     const float* __restrict__ gam,
                     const float* __restrict__ bet,
                     const float* __restrict__ mu,
                     const float* __restrict__ var,
                     const float* __restrict__ res,
                     void* __restrict__ outv)
{
    extern __shared__ char smem[];
    const uint32_t sb = smem_u32(smem);

    const int tid  = threadIdx.x;
    const int warp = tid >> 5, lane = tid & 31;
    const int warp_m = warp >> 2;
    const int warp_n = warp & 3;

    const int n0 = blockIdx.x * BN;
    const int m0 = blockIdx.y * BM;
    const int bz = blockIdx.z;
    const __half* Bh = Bh_ + (size_t)bz * HWP * CC;

    float acc[4][4][4];
#pragma unroll
    for (int i = 0; i < 4; i++)
#pragma unroll
        for (int j = 0; j < 4; j++)
#pragma unroll
            for (int q = 0; q < 4; q++) acc[i][j][q] = 0.f;

    const __half* apt[4];
    const __half* bpt[4];
    uint32_t soff[4];
#pragma unroll
    for (int j = 0; j < 4; j++) {
        int rc = tid + j * 256;
        int row = rc >> 3, c = (rc & 7) * 8;
        soff[j] = (row * LDT + c) * 2;
        apt[j] = Ah + (size_t)(m0 + row) * CC + c;
        bpt[j] = Bh + (size_t)(n0 + row) * CC + c;
    }

    auto stage = [&](int it) {
        const uint32_t st = sb + (it & 1) * STAGE_B;
        const int kt = it * BKE;
#pragma unroll
        for (int j = 0; j < 4; j++) {
            cp_async16(st + soff[j], apt[j] + kt);
            cp_async16(st + TILE_B + soff[j], bpt[j] + kt);
        }
        cp_commit();
    };

    const int lr = lane & 15;
    const int lh = (lane >> 4) * 8;

    stage(0);

    for (int it = 0; it < NKT; it++) {
        if (it + 1 < NKT) {
            stage(it + 1);
            cp_wait<1>();
        } else {
            cp_wait<0>();
        }
        __syncthreads();

        const uint32_t st = sb + (it & 1) * STAGE_B;
#pragma unroll
        for (int kh = 0; kh < 4; kh++) {
            const int k16 = kh * 16;
            uint32_t af[4][4];
#pragma unroll
            for (int mt = 0; mt < 4; mt++)
                ldmx4(af[mt], st + ((warp_m * 64 + mt * 16 + lr) * LDT + k16 + lh) * 2);
            uint32_t bf[2][4];
#pragma unroll
            for (int nt2 = 0; nt2 < 2; nt2++)
                ldmx4(bf[nt2], st + TILE_B +
                      ((warp_n * 32 + nt2 * 16 + lr) * LDT + k16 + lh) * 2);
#pragma unroll
            for (int mt = 0; mt < 4; mt++)
#pragma unroll
                for (int nt = 0; nt < 4; nt++)
                    mma16816(acc[mt][nt], af[mt],
                             bf[nt >> 1][nt & 1], bf[nt >> 1][(nt & 1) + 2]);
        }
        __syncthreads();
    }

    const int qrow = lane >> 2;
    const int qcol = (lane & 3) * 2;
#pragma unroll
    for (int mt = 0; mt < 4; mt++) {
#pragma unroll
        for (int half = 0; half < 2; half++) {
            const int co = m0 + warp_m * 64 + mt * 16 + qrow + half * 8;
            const float sc0 = gam[co] * rsqrtf(var[co] + EPSB);
            const float bi = bet[co] - mu[co] * sc0;
            const float sc = sc0 * INV_S;
            const size_t rbase = (size_t)bz * CHW + (size_t)co * HWP + n0 + warp_n * 32;
#pragma unroll
            for (int nt = 0; nt < 4; nt++) {
                const int nn = nt * 8 + qcol;
                float y0 = silu(acc[mt][nt][half * 2 + 0] * sc + bi);
                float y1 = silu(acc[mt][nt][half * 2 + 1] * sc + bi);
                if (HALF_OUT) {
                    __half* orow = (__half*)outv + rbase;
                    *(__half2*)&orow[nn] = __floats2half2_rn(y0, y1);
                } else {
                    float* orow = (float*)outv + rbase;
                    const float* rrow = res + rbase;
                    y0 += rrow[nn];
                    y1 += rrow[nn + 1];
                    *(float2*)&orow[nn] = make_float2(y0, y1);
                }
            }
        }
    }
}

// ---------------------------------------------------------------------------
// K2: per-(b,nh,h) softmax-attention, k-major smem + trans ldmatrix (R14).
// ---------------------------------------------------------------------------
__global__ __launch_bounds__(256)
void attn_kernel(const __half* __restrict__ Y1, __half* __restrict__ Y2)
{
    const int bid = blockIdx.x;
    const int h  = bid & 63;
    const int nh = (bid >> 6) & 15;
    const int b  = bid >> 10;

    const __half* basep = Y1 + (size_t)b * CHW + (size_t)(nh * HD) * HWP + h * WW;

    __shared__ __half Ak[64 * LDK];    // [k][w]
    __shared__ __half Ps[64 * LDK];    // [k][w]  (unnormalized exp)
    __shared__ float red[4 * 64];
    __shared__ float mx_s[64];
    __shared__ float inv_s[64];

    const int tid = threadIdx.x;
    const int lane = tid & 31, warp = tid >> 5;

    // coalesced load, k-major (no transpose)
#pragma unroll
    for (int j = 0; j < 2; j++) {
        int idx = j * 256 + tid;
        int k = idx >> 3, c = idx & 7;
        uint4 v = *(const uint4*)(basep + (size_t)k * HWP + c * 8);
        *(uint4*)&Ak[k * LDK + c * 8] = v;
    }
    __syncthreads();

    // column softmax: thread (w, seg) handles k in [seg*16, seg*16+16)
    const int w = tid & 63, seg = tid >> 6;
    __half av[16];
    float mx = -1e30f;
#pragma unroll
    for (int i = 0; i < 16; i++) {
        av[i] = Ak[(seg * 16 + i) * LDK + w];
        mx = fmaxf(mx, __half2float(av[i]));
    }
    red[seg * 64 + w] = mx;
    __syncthreads();
    if (tid < 64)
        mx_s[tid] = fmaxf(fmaxf(red[tid], red[64 + tid]),
                          fmaxf(red[128 + tid], red[192 + tid]));
    __syncthreads();

    const float mw = mx_s[w];
    float sum = 0.f;
#pragma unroll
    for (int i = 0; i < 16; i++) {
        float e = __expf(__half2float(av[i]) - mw);
        sum += e;
        Ps[(seg * 16 + i) * LDK + w] = __float2half_rn(e);
    }
    red[seg * 64 + w] = sum;
    __syncthreads();
    if (tid < 64)
        inv_s[tid] = 1.f / (red[tid] + red[64 + tid] + red[128 + tid] + red[192 + tid]);
    __syncthreads();

    // MMA: warp tile 16(w) x 32(v); both operands via trans ldmatrix
    const uint32_t pk = smem_u32(Ps);
    const uint32_t ak = smem_u32(Ak);
    const int m0 = (warp & 3) * 16;        // w base
    const int nw0 = (warp >> 2) * 32;      // v base
    const int kpart = (lane >> 4) * 8 + (lane & 7);
    const int cpart = ((lane >> 3) & 1) * 8;

    float acc[4][4];
#pragma unroll
    for (int i = 0; i < 4; i++)
#pragma unroll
        for (int q = 0; q < 4; q++) acc[i][q] = 0.f;

#pragma unroll
    for (int kh = 0; kh < 4; kh++) {
        const int krow = kh * 16 + kpart;
        uint32_t a[4];
        ldmx4t(a, pk + (krow * LDK + m0 + cpart) * 2);
        uint32_t bf[2][4];
#pragma unroll
        for (int g = 0; g < 2; g++)
            ldmx4t(bf[g], ak + (krow * LDK + nw0 + g * 16 + cpart) * 2);
#pragma unroll
        for (int nt = 0; nt < 4; nt++)
            mma16816(acc[nt], a, bf[nt >> 1][nt & 1], bf[nt >> 1][(nt & 1) + 2]);
    }
    __syncthreads();   // done reading Ak; reuse as output staging

    // scale by inv[w]; stage att^T[v][w] into Ak
    const int qrow = lane >> 2;
    const int qcol = (lane & 3) * 2;
    const float inv0 = inv_s[m0 + qrow];
    const float inv1 = inv_s[m0 + qrow + 8];
#pragma unroll
    for (int nt = 0; nt < 4; nt++) {
        const int v = nw0 + nt * 8 + qcol;
        Ak[v * LDK + m0 + qrow]           = __float2half_rn(acc[nt][0] * inv0);
        Ak[(v + 1) * LDK + m0 + qrow]     = __float2half_rn(acc[nt][1] * inv0);
        Ak[v * LDK + m0 + qrow + 8]       = __float2half_rn(acc[nt][2] * inv1);
        Ak[(v + 1) * LDK + m0 + qrow + 8] = __float2half_rn(acc[nt][3] * inv1);
    }
    __syncthreads();

    // coalesced vector store
    __half* outb = Y2 + (size_t)b * CHW + (size_t)(nh * HD) * HWP + h * WW;
#pragma unroll
    for (int j = 0; j < 2; j++) {
        int idx = j * 256 + tid;
        int v = idx >> 3, c = idx & 7;
        *(uint4*)(outb + (size_t)v * HWP + c * 8) = *(const uint4*)&Ak[v * LDK + c * 8];
    }
}

// ---------------------------------------------------------------------------
// K3 fused: depthwise 3x3 + BN + SiLU + transpose + fp16 convert.
// 2 adjacent pixels per thread via aligned half2 loads: 9 half2-LDS per
// (2px, ch) instead of 18 scalar. fp32 accumulate (precision unchanged).
// ---------------------------------------------------------------------------
__global__ __launch_bounds__(256)
void dwconv_t_kernel(const __half* __restrict__ X,
                     const float* __restrict__ W2,
                     const float* __restrict__ gam,
                     const float* __restrict__ bet,
                     const float* __restrict__ mu,
                     const float* __restrict__ var,
                     __half* __restrict__ Th)
{
    extern __shared__ __half Sh[];     // DWC * 4096 halves
    const int c0 = blockIdx.x * DWC;
    const int b  = blockIdx.y;
    const int tid = threadIdx.x;

    const uint4* src = (const uint4*)(X + ((size_t)b * CC + c0) * HWP);
    uint4* dst = (uint4*)Sh;
#pragma unroll
    for (int j = 0; j < 16; j++)
        dst[j * 256 + tid] = src[j * 256 + tid];

    float w[DWC][9], sc[DWC], bi[DWC];
#pragma unroll
    for (int ch = 0; ch < DWC; ch++) {
        const int c = c0 + ch;
#pragma unroll
        for (int k = 0; k < 9; k++) w[ch][k] = W2[c * 9 + k];
        const float s0 = gam[c] * rsqrtf(var[c] + EPSB);
        sc[ch] = s0;
        bi[ch] = bet[c] - mu[c] * s0;
    }
    __syncthreads();

    __half* outp = Th + (size_t)b * HWP * CC + c0;
#pragma unroll 2
    for (int j = 0; j < 8; j++) {
        const int pr = j * 256 + tid;       // pixel-pair index
        const int p0 = pr * 2;
        const int y = p0 >> 6, x = p0 & 63; // x even

        int roff[3];
        float ml[3], mm[3], mr[3];
        const float cL = (x >= 2) ? 1.f : 0.f;
        const float cR = (x <= 60) ? 1.f : 0.f;
        const int xl = (x >= 2) ? x - 2 : 0;
        const int xr = (x <= 60) ? x + 2 : 60;
#pragma unroll
        for (int dy = 0; dy < 3; dy++) {
            int ry = y + dy - 1;
            bool ok = (unsigned)ry < 64u;
            roff[dy] = ok ? ry * 64 : 0;
            float m = ok ? 1.f : 0.f;
            ml[dy] = m * cL;
            mm[dy] = m;
            mr[dy] = m * cR;
        }

        uint32_t h0[4], h1[4];              // packed fp16x2 outputs
#pragma unroll
        for (int ch = 0; ch < DWC; ch++) {
            const __half* pl = Sh + ch * HWP;
            float a0 = 0.f, a1 = 0.f;
#pragma unroll
            for (int dy = 0; dy < 3; dy++) {
                const __half* row = pl + roff[dy];
                float2 L = __half22float2(*(const __half2*)(row + xl));
                float2 M = __half22float2(*(const __half2*)(row + x));
                float2 R = __half22float2(*(const __half2*)(row + xr));
                float v0 = L.y * ml[dy];
                float v1 = M.x * mm[dy];
                float v2 = M.y * mm[dy];
                float v3 = R.x * mr[dy];
                a0 = fmaf(w[ch][dy * 3 + 0], v0, a0);
                a0 = fmaf(w[ch][dy * 3 + 1], v1, a0);
                a0 = fmaf(w[ch][dy * 3 + 2], v2, a0);
                a1 = fmaf(w[ch][dy * 3 + 0], v1, a1);
                a1 = fmaf(w[ch][dy * 3 + 1], v2, a1);
                a1 = fmaf(w[ch][dy * 3 + 2], v3, a1);
            }
            float s0 = silu(a0 * sc[ch] + bi[ch]) * XSCALE;
            float s1 = silu(a1 * sc[ch] + bi[ch]) * XSCALE;
            ((__half*)h0)[ch] = __float2half_rn(s0);
            ((__half*)h1)[ch] = __float2half_rn(s1);
        }
        *(uint4*)&outp[(size_t)p0 * CC]       = *(uint4*)h0;
        *(uint4*)&outp[(size_t)(p0 + 1) * CC] = *(uint4*)h1;
    }
}

// ---------------------------------------------------------------------------
// Launch. setup_inputs() dict order:
//   0:x 1:w1 2:w2 3:w3 4:g1 5:b1 6:m1 7:v1 8:g2 9:b2 10:m2 11:v2 12:g3 13:b3 14:m3 15:v3
// ---------------------------------------------------------------------------
extern "C" void kernel_launch(void* const* d_in, const int* in_sizes, int n_in,
                              void* d_out, int out_size)
{
    const float* x  = (const float*)d_in[0];
    const float* w1 = (const float*)d_in[1];
    const float* w2 = (const float*)d_in[2];
    const float* w3 = (const float*)d_in[3];
    const float* g1 = (const float*)d_in[4];
    const float* b1 = (const float*)d_in[5];
    const float* m1 = (const float*)d_in[6];
    const float* v1 = (const float*)d_in[7];
    const float* g2 = (const float*)d_in[8];
    const float* b2 = (const float*)d_in[9];
    const float* m2 = (const float*)d_in[10];
    const float* v2 = (const float*)d_in[11];
    const float* g3 = (const float*)d_in[12];
    const float* b3 = (const float*)d_in[13];
    const float* m3 = (const float*)d_in[14];
    const float* v3 = (const float*)d_in[15];
    float* out = (float*)d_out;

    if (!(in_sizes[1] == CC * CC && in_sizes[2] == CC * 9 && in_sizes[3] == CC * CC)) {
        const float* big[2] = {nullptr, nullptr}; int nbig = 0;
        const float* small9216 = nullptr;
        const float* perch[12]; int nper = 0;
        for (int i = 1; i < n_in; i++) {
            if (in_sizes[i] == CC * CC && nbig < 2) big[nbig++] = (const float*)d_in[i];
            else if (in_sizes[i] == CC * 9) small9216 = (const float*)d_in[i];
            else if (in_sizes[i] == CC && nper < 12) perch[nper++] = (const float*)d_in[i];
        }
        w1 = big[0]; w3 = big[1]; w2 = small9216;
        g1 = perch[0]; b1 = perch[1]; m1 = perch[2];  v1 = perch[3];
        g2 = perch[4]; b2 = perch[5]; m2 = perch[6];  v2 = perch[7];
        g3 = perch[8]; b3 = perch[9]; m3 = perch[10]; v3 = perch[11];
    }

    __half *p_y1h, *p_y2h, *p_w1h, *p_w3h, *p_bh;
    cudaGetSymbolAddress((void**)&p_y1h, g_y1h);
    cudaGetSymbolAddress((void**)&p_y2h, g_y2h);
    cudaGetSymbolAddress((void**)&p_w1h, g_w1h);
    cudaGetSymbolAddress((void**)&p_w3h, g_w3h);
    cudaGetSymbolAddress((void**)&p_bh, g_bh);

    cudaFuncSetAttribute(gemm_mma_kernel<true>,
                         cudaFuncAttributeMaxDynamicSharedMemorySize, SMEM_TOT);
    cudaFuncSetAttribute(gemm_mma_kernel<false>,
                         cudaFuncAttributeMaxDynamicSharedMemorySize, SMEM_TOT);
    cudaFuncSetAttribute(dwconv_t_kernel,
                         cudaFuncAttributeMaxDynamicSharedMemorySize, DW_SMEM_H);

    dim3 tgrid(HWP / 32, CC / 64, BB);
    dim3 ggrid(HWP / BN, CC / BM, BB);     // (32, 8, 8)
    dim3 dgrid(CC / DWC, BB);              // (128, 8)

    convert_w2_kernel<<<(CC * CC + 511) / 512, 512>>>(w1, w3, p_w1h, p_w3h);
    transpose_cvt_kernel<<<tgrid, 256>>>(x, p_bh);
    gemm_mma_kernel<true><<<ggrid, 256, SMEM_TOT>>>(p_w1h, p_bh,
                                                    g1, b1, m1, v1, nullptr, p_y1h);
    attn_kernel<<<BB * NHD * HH, 256>>>(p_y1h, p_y2h);
    dwconv_t_kernel<<<dgrid, 256, DW_SMEM_H>>>(p_y2h, w2, g2, b2, m2, v2, p_bh);
    gemm_mma_kernel<false><<<ggrid, 256, SMEM_TOT>>>(p_w3h, p_bh,
                                                     g3, b3, m3, v3, x, out);
}